// round 15
// baseline (speedup 1.0000x reference)
#include <cuda_runtime.h>
#include <cuda.h>
#include <cstdint>

// ---------------------------------------------------------------------------
// Problem dims (fixed by the dataset)
// ---------------------------------------------------------------------------
#define HIDDEN 128
#define BATCH  4096
#define SESS   50
#define KDIM   4096

// GEMM tiling: R14 pipeline (KC=64, NSTAGES=4), warp tile 64x64 (2N x 4ks).
#define BM       64
#define KSPLIT   2
#define KHALF    (KDIM / KSPLIT)   // 2048
#define KC       64                // K floats per stage (2 chunks of 32)
#define NITER    (KHALF / KC)      // 32
#define NSTAGES  4
#define NCONS    8                 // consumer warps
#define NTHREADS (NCONS * 32 + 32) // 288
#define A_CH_BYTES (BM * 32 * 4)       // 8192  per 32-col chunk
#define B_CH_BYTES (HIDDEN * 32 * 4)   // 16384 per 32-col chunk
#define A_ST_BYTES (2 * A_CH_BYTES)    // 16384
#define B_ST_BYTES (2 * B_CH_BYTES)    // 32768
#define STAGE_BYTES (A_ST_BYTES + B_ST_BYTES)         // 49152
#define SM_BAR      (NSTAGES * STAGE_BYTES)           // 196608 (192KB, occ 1)
#define SMEM_DYN    (SM_BAR + 128)

// ---------------------------------------------------------------------------
// Scratch (allocation-free rule: __device__ globals)
// ---------------------------------------------------------------------------
__device__ float g_Rt[HIDDEN * BATCH];          // R^T  [n=128][k=4096]
__device__ float g_Tp[KSPLIT * BATCH * HIDDEN]; // GEMM1 partials, row-major
__device__ float g_Tt[HIDDEN * BATCH];          // T^T  [n=128][k=4096]
__device__ float g_Op[KSPLIT * BATCH * HIDDEN]; // GEMM2 partials, row-major

// ---------------------------------------------------------------------------
// PTX helpers (sm_90-portable; NO tcgen05)
// ---------------------------------------------------------------------------
__device__ __forceinline__ uint32_t smem_u32(const void* p) {
    uint32_t a;
    asm("{ .reg .u64 t; cvta.to.shared.u64 t, %1; cvt.u32.u64 %0, t; }" : "=r"(a) : "l"(p));
    return a;
}
__device__ __forceinline__ uint32_t elect_one() {
    uint32_t p;
    asm volatile("{\n\t.reg .pred p;\n\telect.sync _|p, 0xFFFFFFFF;\n\tselp.b32 %0, 1, 0, p;\n\t}" : "=r"(p));
    return p;
}
#define MBAR_INIT(addr, cnt) \
    asm volatile("mbarrier.init.shared.b64 [%0], %1;" :: "r"((uint32_t)(addr)), "r"((uint32_t)(cnt)) : "memory")
#define MBAR_ARRIVE(addr) \
    asm volatile("mbarrier.arrive.shared.b64 _, [%0];" :: "r"((uint32_t)(addr)) : "memory")
#define MBAR_EXPECT_TX(addr, bytes) \
    asm volatile("mbarrier.arrive.expect_tx.shared.b64 _, [%0], %1;" :: "r"((uint32_t)(addr)), "r"((uint32_t)(bytes)) : "memory")
#define FENCE_PROXY_ASYNC() asm volatile("fence.proxy.async;" ::: "memory")

#define MBAR_WAIT(addr, parity) do {                                             \
    uint32_t _m = (uint32_t)(addr); uint32_t _p = (uint32_t)(parity);            \
    asm volatile("{\n\t.reg .pred P1;\n\t"                                       \
        "WL_%=:\n\t"                                                             \
        "mbarrier.try_wait.parity.acquire.cta.shared::cta.b64 P1, [%0], %1, 0x989680;\n\t" \
        "@P1 bra.uni WD_%=;\n\t"                                                 \
        "bra.uni WL_%=;\n\t"                                                     \
        "WD_%=:\n\t}" :: "r"(_m), "r"(_p) : "memory");                           \
} while (0)

#define MBAR_WAIT_RELAXED(addr, parity) do {                                     \
    uint32_t _m = (uint32_t)(addr); uint32_t _p = (uint32_t)(parity);            \
    asm volatile("{\n\t.reg .pred P1;\n\t"                                       \
        "WL_%=:\n\t"                                                             \
        "mbarrier.try_wait.parity.relaxed.cta.shared::cta.b64 P1, [%0], %1, 0x989680;\n\t" \
        "@P1 bra.uni WD_%=;\n\t"                                                 \
        "bra.uni WL_%=;\n\t"                                                     \
        "WD_%=:\n\t}" :: "r"(_m), "r"(_p) : "memory");                           \
} while (0)

#define TMA_LOAD2D(smem_addr, tmap_ptr, cx, cy, mbar)                                            \
    asm volatile("cp.async.bulk.tensor.2d.shared::cta.global.tile.mbarrier::complete_tx::bytes " \
                 "[%0], [%1, {%2, %3}], [%4];"                                                   \
                 :: "r"((uint32_t)(smem_addr)), "l"(tmap_ptr), "r"((int)(cx)), "r"((int)(cy)),   \
                    "r"((uint32_t)(mbar)) : "memory")

__device__ __forceinline__ void ldmatrix_x4(uint32_t* r, uint32_t addr) {
    asm volatile("ldmatrix.sync.aligned.m8n8.x4.shared.b16 {%0,%1,%2,%3}, [%4];"
                 : "=r"(r[0]), "=r"(r[1]), "=r"(r[2]), "=r"(r[3]) : "r"(addr));
}
__device__ __forceinline__ void mma_tf32(float* c,
                                         uint32_t a0, uint32_t a1, uint32_t a2, uint32_t a3,
                                         uint32_t b0, uint32_t b1) {
    asm volatile("mma.sync.aligned.m16n8k8.row.col.f32.tf32.tf32.f32 "
                 "{%0,%1,%2,%3}, {%4,%5,%6,%7}, {%8,%9}, {%0,%1,%2,%3};"
                 : "+f"(c[0]), "+f"(c[1]), "+f"(c[2]), "+f"(c[3])
                 : "r"(a0), "r"(a1), "r"(a2), "r"(a3), "r"(b0), "r"(b1));
}

// ---------------------------------------------------------------------------
// Kernel 1: gather+sum, output TRANSPOSED: Rt[h][b] = sum_s emb[items[b,s]][h]
// 128 blocks x 1024 threads; ONE WARP PER SESSION ROW; float4 loads.
// ---------------------------------------------------------------------------
__global__ __launch_bounds__(1024, 1)
void gather_t_kernel(const float* __restrict__ emb,
                     const int* __restrict__ items,
                     float* __restrict__ Rt) {
    __shared__ float sm[32][132];
    const int t  = threadIdx.x;
    const int w  = t >> 5;
    const int l  = t & 31;
    const int b0 = blockIdx.x * 32;

    const int* it = items + (b0 + w) * SESS;
    float4 acc = make_float4(0.f, 0.f, 0.f, 0.f);
#pragma unroll 10
    for (int s = 0; s < SESS; ++s) {
        const long long idx = (long long)it[s];
        const float4 v = *(const float4*)&emb[idx * HIDDEN + l * 4];
        acc.x += v.x; acc.y += v.y; acc.z += v.z; acc.w += v.w;
    }
    *(float4*)&sm[w][l * 4] = acc;
    __syncthreads();

#pragma unroll
    for (int i = 0; i < 4; ++i) {
        const int hh = w * 4 + i;
        Rt[(size_t)hh * BATCH + b0 + l] = sm[l][hh];
    }
}

// ---------------------------------------------------------------------------
// GEMM (partial K):  Cp[kh] = Amat[:, kh-half] @ B[kh-half]
// Grid 128: kh = bx & 1, mtile = bx >> 1.  288 threads, occ 1 (192KB smem):
// 8 consumer warps (2N x 4 K-interleave, warp tile 64x64) + 1 TMA warp.
// KC=64 per stage as two 32-col chunks.  B fragments are NOT duplicated.
// ---------------------------------------------------------------------------
__global__ __launch_bounds__(NTHREADS, 1)
void gemm_part_kernel(const __grid_constant__ CUtensorMap tA,
                      const __grid_constant__ CUtensorMap tB,
                      float* __restrict__ Cp) {
    extern __shared__ char smem[];
    const uint32_t sb = smem_u32(smem);
    const int tid = threadIdx.x;
    const int wid = tid >> 5;
    const int l   = tid & 31;
    const int kh    = blockIdx.x & 1;
    const int mtile = blockIdx.x >> 1;
    const int m0    = mtile * BM;

    if (tid == 0) {
#pragma unroll
        for (int s = 0; s < NSTAGES; ++s) {
            MBAR_INIT(sb + SM_BAR + s * 8, 1);          // full: tx-based
            MBAR_INIT(sb + SM_BAR + 64 + s * 8, NCONS); // empty: 8 consumer warps
        }
        FENCE_PROXY_ASYNC();
    }
    __syncthreads();

    if (wid == NCONS) {
        // -------- producer: 4 TMA loads per stage (2 chunks x {A,B}) --------
        if (elect_one()) {
            int s = 0, ph = 1;
            for (int it = 0; it < NITER; ++it) {
                MBAR_WAIT_RELAXED(sb + SM_BAR + 64 + s * 8, ph);
                MBAR_EXPECT_TX(sb + SM_BAR + s * 8, STAGE_BYTES);
                const int kc = kh * KHALF + it * KC;
                const uint32_t st = sb + s * STAGE_BYTES;
                TMA_LOAD2D(st,                           &tA, kc,      m0, sb + SM_BAR + s * 8);
                TMA_LOAD2D(st + A_CH_BYTES,              &tA, kc + 32, m0, sb + SM_BAR + s * 8);
                TMA_LOAD2D(st + A_ST_BYTES,              &tB, kc,      0,  sb + SM_BAR + s * 8);
                TMA_LOAD2D(st + A_ST_BYTES + B_CH_BYTES, &tB, kc + 32, 0,  sb + SM_BAR + s * 8);
                if (++s == NSTAGES) { s = 0; ph ^= 1; }
            }
        }
        return;
    }

    // -------- consumers: 8 warps = 2N x 4(K-interleave); warp tile 64x64 -----
    const int wn = wid & 1;           // N half (64 cols)
    const int ws = wid >> 1;          // ks slot 0..3 (one k8 per warp per chunk)
    const int g = l >> 2, tq = l & 3;
    const int j = l >> 3, r = l & 7;

    // ldmatrix per-lane address components (byte offsets within a chunk)
    const int aRow0 = (j & 1) * 8 + r;                // base row group 0..15
    const uint32_t aSw   = (uint32_t)((aRow0 & 7) << 4);   // (row+16m)&7 == row&7
    const uint32_t aKsel = (uint32_t)((j >> 1) << 4);
    const int bRowBase = wn * 64 + (j >> 1) * 8 + r;
    const uint32_t bKsel = (uint32_t)((j & 1) << 4);
    const uint32_t kb = (uint32_t)(ws * 32);          // this warp's k8 slot

    float acc[4][8][4];
#pragma unroll
    for (int a = 0; a < 4; ++a)
#pragma unroll
        for (int b = 0; b < 8; ++b)
#pragma unroll
            for (int c = 0; c < 4; ++c) acc[a][b][c] = 0.f;

    int s = 0, ph = 0;
    for (int it = 0; it < NITER; ++it) {
        MBAR_WAIT(sb + SM_BAR + s * 8, ph);
        const uint32_t stBase = sb + s * STAGE_BYTES;

#pragma unroll
        for (int ch = 0; ch < 2; ++ch) {
            const uint32_t aBase = stBase + ch * A_CH_BYTES;
            const uint32_t bBase = stBase + A_ST_BYTES + ch * B_CH_BYTES;

            uint32_t af[4][4];
#pragma unroll
            for (int mt = 0; mt < 4; ++mt)
                ldmatrix_x4(af[mt],
                            aBase + (uint32_t)((aRow0 + mt * 16) * 128) + ((kb + aKsel) ^ aSw));
            uint32_t bf[4][4];
#pragma unroll
            for (int nt16 = 0; nt16 < 4; ++nt16) {
                const int nrow = bRowBase + nt16 * 16;
                ldmatrix_x4(bf[nt16],
                            bBase + (uint32_t)(nrow * 128) + ((kb + bKsel) ^ (uint32_t)((nrow & 7) << 4)));
            }
#pragma unroll
            for (int mt = 0; mt < 4; ++mt)
#pragma unroll
                for (int nt = 0; nt < 8; ++nt) {
                    const uint32_t* bp = bf[nt >> 1] + (nt & 1) * 2;
                    mma_tf32(acc[mt][nt], af[mt][0], af[mt][1], af[mt][2], af[mt][3],
                             bp[0], bp[1]);
                }
        }
        if (elect_one()) MBAR_ARRIVE(sb + SM_BAR + 64 + s * 8);
        if (++s == NSTAGES) { s = 0; ph ^= 1; }
    }

    // -------- epilogue: 4-way ks reduction through dead stage smem -----------
    asm volatile("bar.sync 1, %0;" :: "n"(NCONS * 32) : "memory");
    float* red = (float*)smem;   // 3 regions x (2 wn x 32 lanes x 128 f) = 96KB
    const int rbase = (wn * 32 + l) * 128;
    if (ws > 0) {
        float* reg = red + (ws - 1) * 8192 + rbase;
#pragma unroll
        for (int mt = 0; mt < 4; ++mt)
#pragma unroll
            for (int nt = 0; nt < 8; ++nt) {
                float* d = reg + (mt * 8 + nt) * 4;
                d[0] = acc[mt][nt][0]; d[1] = acc[mt][nt][1];
                d[2] = acc[mt][nt][2]; d[3] = acc[mt][nt][3];
            }
    }
    asm volatile("bar.sync 1, %0;" :: "n"(NCONS * 32) : "memory");
    if (ws == 0) {
        float* outp = Cp + (size_t)kh * BATCH * HIDDEN;
#pragma unroll
        for (int mt = 0; mt < 4; ++mt)
#pragma unroll
            for (int nt = 0; nt < 8; ++nt) {
                const int e = (mt * 8 + nt) * 4;
                float4 v = make_float4(acc[mt][nt][0], acc[mt][nt][1],
                                       acc[mt][nt][2], acc[mt][nt][3]);
#pragma unroll
                for (int wsr = 0; wsr < 3; ++wsr) {
                    const float* d = red + wsr * 8192 + rbase + e;
                    v.x += d[0]; v.y += d[1]; v.z += d[2]; v.w += d[3];
                }
                const int row = m0 + mt * 16 + g;
                const int col = wn * 64 + nt * 8 + tq * 2;
                *(float2*)&outp[(size_t)row * HIDDEN + col]       = make_float2(v.x, v.y);
                *(float2*)&outp[(size_t)(row + 8) * HIDDEN + col] = make_float2(v.z, v.w);
            }
    }
}

// ---------------------------------------------------------------------------
// reduce_T: Tt[n][b] = Tp0[b][n] + Tp1[b][n]   (transpose + add)
// ---------------------------------------------------------------------------
__global__ __launch_bounds__(256, 1)
void reduce_t_kernel(const float* __restrict__ Tp, float* __restrict__ Tt) {
    __shared__ float sm[32][129];
    const int t  = threadIdx.x;
    const int b0 = blockIdx.x * 32;
    const int rr = t >> 5, c4 = t & 31;
#pragma unroll
    for (int i = 0; i < 4; ++i) {
        const int row = rr + 8 * i;
        const size_t off = ((size_t)(b0 + row) * HIDDEN) + c4 * 4;
        float4 a = *(const float4*)&Tp[off];
        float4 b = *(const float4*)&Tp[(size_t)BATCH * HIDDEN + off];
        sm[row][c4 * 4 + 0] = a.x + b.x;
        sm[row][c4 * 4 + 1] = a.y + b.y;
        sm[row][c4 * 4 + 2] = a.z + b.z;
        sm[row][c4 * 4 + 3] = a.w + b.w;
    }
    __syncthreads();
    const int w = t >> 5, l = t & 31;
#pragma unroll
    for (int i = 0; i < 16; ++i) {
        const int n = w + 8 * i;
        Tt[(size_t)n * BATCH + b0 + l] = sm[l][n];
    }
}

// ---------------------------------------------------------------------------
// final_norm: out[b] = normalize(Op0[b] + Op1[b])  (row L2), one warp per row
// ---------------------------------------------------------------------------
__global__ __launch_bounds__(256, 1)
void final_norm_kernel(const float* __restrict__ Op, float* __restrict__ outp) {
    const int t   = threadIdx.x;
    const int row = blockIdx.x * 8 + (t >> 5);
    const int l   = t & 31;
    const size_t off = (size_t)row * HIDDEN + l * 4;
    float4 a = *(const float4*)&Op[off];
    float4 b = *(const float4*)&Op[(size_t)BATCH * HIDDEN + off];
    float4 v = make_float4(a.x + b.x, a.y + b.y, a.z + b.z, a.w + b.w);
    float ss = v.x * v.x + v.y * v.y + v.z * v.z + v.w * v.w;
#pragma unroll
    for (int o = 16; o > 0; o >>= 1) ss += __shfl_xor_sync(0xFFFFFFFFu, ss, o);
    const float sc = rsqrtf(ss);
    v.x *= sc; v.y *= sc; v.z *= sc; v.w *= sc;
    *(float4*)&outp[off] = v;
}

// ---------------------------------------------------------------------------
// Host: tensormaps via driver entry point (through cudart; host-only, capture-safe)
// ---------------------------------------------------------------------------
typedef CUresult (*EncodeTiledFn)(CUtensorMap*, CUtensorMapDataType, cuuint32_t, void*,
                                  const cuuint64_t*, const cuuint64_t*, const cuuint32_t*,
                                  const cuuint32_t*, CUtensorMapInterleave, CUtensorMapSwizzle,
                                  CUtensorMapL2promotion, CUtensorMapFloatOOBfill);

static void make_map_2d(EncodeTiledFn enc, CUtensorMap* m, void* ptr,
                        uint64_t dim0, uint64_t dim1, uint32_t box0, uint32_t box1) {
    cuuint64_t dims[2]    = {dim0, dim1};
    cuuint64_t strides[1] = {dim0 * sizeof(float)};
    cuuint32_t box[2]     = {box0, box1};
    cuuint32_t estr[2]    = {1, 1};
    enc(m, CU_TENSOR_MAP_DATA_TYPE_FLOAT32, 2, ptr, dims, strides, box, estr,
        CU_TENSOR_MAP_INTERLEAVE_NONE, CU_TENSOR_MAP_SWIZZLE_128B,
        CU_TENSOR_MAP_L2_PROMOTION_L2_128B, CU_TENSOR_MAP_FLOAT_OOB_FILL_NONE);
}

// ---------------------------------------------------------------------------
// kernel_launch: inputs in metadata order:
//   d_in[0] item_embedding f32 (100000,128); d_in[1] items i32 (4096,50);
//   d_in[2] A f32 (4096,4096); d_in[3] D f32 (4096,4096); d_in[4] unused.
// Output: f32 (4096, 128)
// ---------------------------------------------------------------------------
extern "C" void kernel_launch(void* const* d_in, const int* in_sizes, int n_in,
                              void* d_out, int out_size) {
    const float* emb   = (const float*)d_in[0];
    const int*   items = (const int*)d_in[1];
    float*       A     = (float*)d_in[2];
    float*       D     = (float*)d_in[3];
    float*       out   = (float*)d_out;

    float *Rt, *Tp, *Tt, *Op;
    cudaGetSymbolAddress((void**)&Rt, g_Rt);
    cudaGetSymbolAddress((void**)&Tp, g_Tp);
    cudaGetSymbolAddress((void**)&Tt, g_Tt);
    cudaGetSymbolAddress((void**)&Op, g_Op);

    void* fn = nullptr;
    cudaDriverEntryPointQueryResult qr;
    cudaGetDriverEntryPoint("cuTensorMapEncodeTiled", &fn, cudaEnableDefault, &qr);
    EncodeTiledFn enc = (EncodeTiledFn)fn;

    CUtensorMap mA, mR, mD, mT;
    make_map_2d(enc, &mA, A,  KDIM, BATCH,  32, BM);      // A  [4096 m][4096 k]
    make_map_2d(enc, &mR, Rt, BATCH, HIDDEN, 32, HIDDEN); // Rt [128 n][4096 k]
    make_map_2d(enc, &mD, D,  KDIM, BATCH,  32, BM);      // D
    make_map_2d(enc, &mT, Tt, BATCH, HIDDEN, 32, HIDDEN); // Tt

    cudaFuncSetAttribute(gemm_part_kernel, cudaFuncAttributeMaxDynamicSharedMemorySize, SMEM_DYN);

    // 1) R^T = gather-sum (transposed; warp-per-row float4)
    gather_t_kernel<<<BATCH / 32, 1024>>>(emb, items, Rt);
    // 2) Tp[kh] = A[:, kh] @ R[kh]  (K-split partials)
    gemm_part_kernel<<<(BATCH / BM) * KSPLIT, NTHREADS, SMEM_DYN>>>(mA, mR, Tp);
    // 3) Tt = transpose(Tp0 + Tp1)
    reduce_t_kernel<<<BATCH / 32, 256>>>(Tp, Tt);
    // 4) Op[kh] = D[:, kh] @ T[kh]
    gemm_part_kernel<<<(BATCH / BM) * KSPLIT, NTHREADS, SMEM_DYN>>>(mD, mT, Op);
    // 5) out = normalize_rows(Op0 + Op1)
    final_norm_kernel<<<BATCH / 8, 256>>>(Op, out);
}

// round 16
// speedup vs baseline: 1.0418x; 1.0418x over previous
#include <cuda_runtime.h>
#include <cuda.h>
#include <cstdint>

// ---------------------------------------------------------------------------
// Problem dims (fixed by the dataset)
// ---------------------------------------------------------------------------
#define HIDDEN 128
#define BATCH  4096
#define SESS   50
#define KDIM   4096

// GEMM tiling: R14 validated config (KC=64 via 2 chunks, NSTAGES=4, occ 1).
#define BM       64
#define KSPLIT   2
#define KHALF    (KDIM / KSPLIT)   // 2048
#define KC       64                // K floats per stage (2 chunks of 32)
#define NITER    (KHALF / KC)      // 32
#define NSTAGES  4
#define NCONS    8                 // consumer warps
#define NTHREADS (NCONS * 32 + 32) // 288
#define A_CH_BYTES (BM * 32 * 4)       // 8192  per 32-col chunk
#define B_CH_BYTES (HIDDEN * 32 * 4)   // 16384 per 32-col chunk
#define A_ST_BYTES (2 * A_CH_BYTES)    // 16384
#define B_ST_BYTES (2 * B_CH_BYTES)    // 32768
#define STAGE_BYTES (A_ST_BYTES + B_ST_BYTES)         // 49152
#define SM_BAR      (NSTAGES * STAGE_BYTES)           // 196608 (192KB, occ 1)
#define SMEM_DYN    (SM_BAR + 128)

// ---------------------------------------------------------------------------
// Scratch (allocation-free rule: __device__ globals)
// ---------------------------------------------------------------------------
__device__ float g_Rt[HIDDEN * BATCH];          // R^T  [n=128][k=4096]
__device__ float g_Tp[KSPLIT * BATCH * HIDDEN]; // GEMM1 partials, row-major
__device__ float g_Tt[HIDDEN * BATCH];          // T^T  [n=128][k=4096]
__device__ float g_Op[KSPLIT * BATCH * HIDDEN]; // GEMM2 partials, row-major

// ---------------------------------------------------------------------------
// PTX helpers (sm_90-portable; NO tcgen05)
// ---------------------------------------------------------------------------
__device__ __forceinline__ uint32_t smem_u32(const void* p) {
    uint32_t a;
    asm("{ .reg .u64 t; cvta.to.shared.u64 t, %1; cvt.u32.u64 %0, t; }" : "=r"(a) : "l"(p));
    return a;
}
__device__ __forceinline__ uint32_t elect_one() {
    uint32_t p;
    asm volatile("{\n\t.reg .pred p;\n\telect.sync _|p, 0xFFFFFFFF;\n\tselp.b32 %0, 1, 0, p;\n\t}" : "=r"(p));
    return p;
}
#define MBAR_INIT(addr, cnt) \
    asm volatile("mbarrier.init.shared.b64 [%0], %1;" :: "r"((uint32_t)(addr)), "r"((uint32_t)(cnt)) : "memory")
#define MBAR_ARRIVE(addr) \
    asm volatile("mbarrier.arrive.shared.b64 _, [%0];" :: "r"((uint32_t)(addr)) : "memory")
#define MBAR_EXPECT_TX(addr, bytes) \
    asm volatile("mbarrier.arrive.expect_tx.shared.b64 _, [%0], %1;" :: "r"((uint32_t)(addr)), "r"((uint32_t)(bytes)) : "memory")
#define FENCE_PROXY_ASYNC() asm volatile("fence.proxy.async;" ::: "memory")

#define MBAR_WAIT(addr, parity) do {                                             \
    uint32_t _m = (uint32_t)(addr); uint32_t _p = (uint32_t)(parity);            \
    asm volatile("{\n\t.reg .pred P1;\n\t"                                       \
        "WL_%=:\n\t"                                                             \
        "mbarrier.try_wait.parity.acquire.cta.shared::cta.b64 P1, [%0], %1, 0x989680;\n\t" \
        "@P1 bra.uni WD_%=;\n\t"                                                 \
        "bra.uni WL_%=;\n\t"                                                     \
        "WD_%=:\n\t}" :: "r"(_m), "r"(_p) : "memory");                           \
} while (0)

#define MBAR_WAIT_RELAXED(addr, parity) do {                                     \
    uint32_t _m = (uint32_t)(addr); uint32_t _p = (uint32_t)(parity);            \
    asm volatile("{\n\t.reg .pred P1;\n\t"                                       \
        "WL_%=:\n\t"                                                             \
        "mbarrier.try_wait.parity.relaxed.cta.shared::cta.b64 P1, [%0], %1, 0x989680;\n\t" \
        "@P1 bra.uni WD_%=;\n\t"                                                 \
        "bra.uni WL_%=;\n\t"                                                     \
        "WD_%=:\n\t}" :: "r"(_m), "r"(_p) : "memory");                           \
} while (0)

#define TMA_LOAD2D(smem_addr, tmap_ptr, cx, cy, mbar)                                            \
    asm volatile("cp.async.bulk.tensor.2d.shared::cta.global.tile.mbarrier::complete_tx::bytes " \
                 "[%0], [%1, {%2, %3}], [%4];"                                                   \
                 :: "r"((uint32_t)(smem_addr)), "l"(tmap_ptr), "r"((int)(cx)), "r"((int)(cy)),   \
                    "r"((uint32_t)(mbar)) : "memory")

__device__ __forceinline__ void ldmatrix_x4(uint32_t* r, uint32_t addr) {
    asm volatile("ldmatrix.sync.aligned.m8n8.x4.shared.b16 {%0,%1,%2,%3}, [%4];"
                 : "=r"(r[0]), "=r"(r[1]), "=r"(r[2]), "=r"(r[3]) : "r"(addr));
}
__device__ __forceinline__ void mma_tf32(float* c,
                                         uint32_t a0, uint32_t a1, uint32_t a2, uint32_t a3,
                                         uint32_t b0, uint32_t b1) {
    asm volatile("mma.sync.aligned.m16n8k8.row.col.f32.tf32.tf32.f32 "
                 "{%0,%1,%2,%3}, {%4,%5,%6,%7}, {%8,%9}, {%0,%1,%2,%3};"
                 : "+f"(c[0]), "+f"(c[1]), "+f"(c[2]), "+f"(c[3])
                 : "r"(a0), "r"(a1), "r"(a2), "r"(a3), "r"(b0), "r"(b1));
}

// ---------------------------------------------------------------------------
// Kernel 1: gather+sum, output TRANSPOSED: Rt[h][b] = sum_s emb[items[b,s]][h]
// 128 blocks x 1024 threads; ONE WARP PER SESSION ROW; float4 loads.
// ---------------------------------------------------------------------------
__global__ __launch_bounds__(1024, 1)
void gather_t_kernel(const float* __restrict__ emb,
                     const int* __restrict__ items,
                     float* __restrict__ Rt) {
    __shared__ float sm[32][132];
    const int t  = threadIdx.x;
    const int w  = t >> 5;
    const int l  = t & 31;
    const int b0 = blockIdx.x * 32;

    const int* it = items + (b0 + w) * SESS;
    float4 acc = make_float4(0.f, 0.f, 0.f, 0.f);
#pragma unroll 10
    for (int s = 0; s < SESS; ++s) {
        const long long idx = (long long)it[s];
        const float4 v = *(const float4*)&emb[idx * HIDDEN + l * 4];
        acc.x += v.x; acc.y += v.y; acc.z += v.z; acc.w += v.w;
    }
    *(float4*)&sm[w][l * 4] = acc;
    __syncthreads();

#pragma unroll
    for (int i = 0; i < 4; ++i) {
        const int hh = w * 4 + i;
        Rt[(size_t)hh * BATCH + b0 + l] = sm[l][hh];
    }
}

// ---------------------------------------------------------------------------
// GEMM (partial K):  Cp[kh] = Amat[:, kh-half] @ B[kh-half]
// Grid 128: kh = bx & 1, mtile = bx >> 1.  288 threads, occ 1 (192KB smem):
// 8 consumer warps (2M x 2N x 2 K-interleave, warp tile 32x64) + 1 TMA warp.
// R16: cross-stage fragment double-buffering — chunk frags are prefetched one
// step ahead so LDSM latency overlaps the previous chunk's MMA stream.
// ---------------------------------------------------------------------------
__global__ __launch_bounds__(NTHREADS, 1)
void gemm_part_kernel(const __grid_constant__ CUtensorMap tA,
                      const __grid_constant__ CUtensorMap tB,
                      float* __restrict__ Cp) {
    extern __shared__ char smem[];
    const uint32_t sb = smem_u32(smem);
    const int tid = threadIdx.x;
    const int wid = tid >> 5;
    const int l   = tid & 31;
    const int kh    = blockIdx.x & 1;
    const int mtile = blockIdx.x >> 1;
    const int m0    = mtile * BM;

    if (tid == 0) {
#pragma unroll
        for (int s = 0; s < NSTAGES; ++s) {
            MBAR_INIT(sb + SM_BAR + s * 8, 1);          // full: tx-based
            MBAR_INIT(sb + SM_BAR + 64 + s * 8, NCONS); // empty: 8 consumer warps
        }
        FENCE_PROXY_ASYNC();
    }
    __syncthreads();

    if (wid == NCONS) {
        // -------- producer: 4 TMA loads per stage (2 chunks x {A,B}) --------
        if (elect_one()) {
            int s = 0, ph = 1;
            for (int it = 0; it < NITER; ++it) {
                MBAR_WAIT_RELAXED(sb + SM_BAR + 64 + s * 8, ph);
                MBAR_EXPECT_TX(sb + SM_BAR + s * 8, STAGE_BYTES);
                const int kc = kh * KHALF + it * KC;
                const uint32_t st = sb + s * STAGE_BYTES;
                TMA_LOAD2D(st,                           &tA, kc,      m0, sb + SM_BAR + s * 8);
                TMA_LOAD2D(st + A_CH_BYTES,              &tA, kc + 32, m0, sb + SM_BAR + s * 8);
                TMA_LOAD2D(st + A_ST_BYTES,              &tB, kc,      0,  sb + SM_BAR + s * 8);
                TMA_LOAD2D(st + A_ST_BYTES + B_CH_BYTES, &tB, kc + 32, 0,  sb + SM_BAR + s * 8);
                if (++s == NSTAGES) { s = 0; ph ^= 1; }
            }
        }
        return;
    }

    // -------- consumers: 8 warps = 2M x 2N x 2(K-interleave) --------
    const int wm = wid & 1;           // M half (32 rows)
    const int wn = (wid >> 1) & 1;    // N half (64 cols)
    const int ws = wid >> 2;          // K-interleave half within each chunk
    const int g = l >> 2, tq = l & 3;
    const int j = l >> 3, r = l & 7;

    // ldmatrix per-lane address components (byte offsets within a chunk)
    const int aRow0 = wm * 32 + (j & 1) * 8 + r;
    const uint32_t aOff0 = (uint32_t)(aRow0 * 128);
    const uint32_t aOff1 = (uint32_t)((aRow0 + 16) * 128);
    const uint32_t aSw0  = (uint32_t)((aRow0 & 7) << 4);
    const uint32_t aSw1  = (uint32_t)(((aRow0 + 16) & 7) << 4);
    const uint32_t aKsel = (uint32_t)((j >> 1) << 4);
    const int bRowBase = wn * 64 + (j >> 1) * 8 + r;
    const uint32_t bKsel = (uint32_t)((j & 1) << 4);

    float acc[2][8][4];
#pragma unroll
    for (int a = 0; a < 2; ++a)
#pragma unroll
        for (int b = 0; b < 8; ++b)
#pragma unroll
            for (int c = 0; c < 4; ++c) acc[a][b][c] = 0.f;

    // Fragment chunk loader / MMA helpers
    auto load_chunk = [&](uint32_t aBase, uint32_t bBase,
                          uint32_t (&af)[2][2][4], uint32_t (&bf)[2][4][4]) {
#pragma unroll
        for (int ki = 0; ki < 2; ++ki) {
            const uint32_t kb = (uint32_t)((ws * 2 + ki) * 32);
            ldmatrix_x4(af[ki][0], aBase + aOff0 + ((kb + aKsel) ^ aSw0));
            ldmatrix_x4(af[ki][1], aBase + aOff1 + ((kb + aKsel) ^ aSw1));
#pragma unroll
            for (int nt16 = 0; nt16 < 4; ++nt16) {
                const int nrow = bRowBase + nt16 * 16;
                ldmatrix_x4(bf[ki][nt16],
                            bBase + (uint32_t)(nrow * 128) + ((kb + bKsel) ^ (uint32_t)((nrow & 7) << 4)));
            }
        }
    };
    auto mma_chunk = [&](uint32_t (&af)[2][2][4], uint32_t (&bf)[2][4][4]) {
#pragma unroll
        for (int ki = 0; ki < 2; ++ki)
#pragma unroll
            for (int mt = 0; mt < 2; ++mt)
#pragma unroll
                for (int nt = 0; nt < 8; ++nt) {
                    const uint32_t* bp = bf[ki][nt >> 1] + (nt & 1) * 2;
                    mma_tf32(acc[mt][nt],
                             af[ki][mt][0], af[ki][mt][1], af[ki][mt][2], af[ki][mt][3],
                             bp[0], bp[1]);
                }
    };

    uint32_t afA[2][2][4], bfA[2][4][4];   // buffer A: current chunk0 / next-stage chunk0
    uint32_t afB[2][2][4], bfB[2][4][4];   // buffer B: current chunk1

    // Prologue: wait stage 0, load its chunk0
    MBAR_WAIT(sb + SM_BAR + 0, 0);
    load_chunk(sb, sb + A_ST_BYTES, afA, bfA);

    int s = 0, ph = 0;
    for (int it = 0; it < NITER; ++it) {
        const uint32_t stBase = sb + s * STAGE_BYTES;

        // Prefetch chunk1 of current stage (last smem reads of stage s)
        load_chunk(stBase + A_CH_BYTES, stBase + A_ST_BYTES + B_CH_BYTES, afB, bfB);
        if (elect_one()) MBAR_ARRIVE(sb + SM_BAR + 64 + s * 8);   // stage s fully read

        // MMA chunk0 (overlaps chunk1 LDSM completion)
        mma_chunk(afA, bfA);

        // Advance pipeline: wait next stage (fast path — producer runs ahead),
        // prefetch its chunk0 so its LDSM latency overlaps MMA chunk1.
        const int  sn  = (s + 1 == NSTAGES) ? 0 : s + 1;
        const int  phn = (s + 1 == NSTAGES) ? (ph ^ 1) : ph;
        if (it + 1 < NITER) {
            MBAR_WAIT(sb + SM_BAR + sn * 8, phn);
            const uint32_t stN = sb + sn * STAGE_BYTES;
            load_chunk(stN, stN + A_ST_BYTES, afA, bfA);
        }

        // MMA chunk1
        mma_chunk(afB, bfB);

        s = sn; ph = phn;
    }

    // -------- epilogue: combine the two ws-halves through smem, then store ----
    asm volatile("bar.sync 1, %0;" :: "n"(NCONS * 32) : "memory");
    float* red = (float*)smem;   // 4 groups x 32 lanes x 64 floats = 32KB
    const int rbase = ((wm * 2 + wn) * 32 + l) * 64;
    if (ws == 1) {
#pragma unroll
        for (int mt = 0; mt < 2; ++mt)
#pragma unroll
            for (int nt = 0; nt < 8; ++nt) {
                float* d = red + rbase + (mt * 8 + nt) * 4;
                d[0] = acc[mt][nt][0]; d[1] = acc[mt][nt][1];
                d[2] = acc[mt][nt][2]; d[3] = acc[mt][nt][3];
            }
    }
    asm volatile("bar.sync 1, %0;" :: "n"(NCONS * 32) : "memory");
    if (ws == 0) {
        float* outp = Cp + (size_t)kh * BATCH * HIDDEN;
#pragma unroll
        for (int mt = 0; mt < 2; ++mt)
#pragma unroll
            for (int nt = 0; nt < 8; ++nt) {
                const float* d = red + rbase + (mt * 8 + nt) * 4;
                const int row = m0 + wm * 32 + mt * 16 + g;
                const int col = wn * 64 + nt * 8 + tq * 2;
                float2 v0 = make_float2(acc[mt][nt][0] + d[0], acc[mt][nt][1] + d[1]);
                float2 v1 = make_float2(acc[mt][nt][2] + d[2], acc[mt][nt][3] + d[3]);
                *(float2*)&outp[(size_t)row * HIDDEN + col]       = v0;
                *(float2*)&outp[(size_t)(row + 8) * HIDDEN + col] = v1;
            }
    }
}

// ---------------------------------------------------------------------------
// reduce_T: Tt[n][b] = Tp0[b][n] + Tp1[b][n]   (transpose + add)
// ---------------------------------------------------------------------------
__global__ __launch_bounds__(256, 1)
void reduce_t_kernel(const float* __restrict__ Tp, float* __restrict__ Tt) {
    __shared__ float sm[32][129];
    const int t  = threadIdx.x;
    const int b0 = blockIdx.x * 32;
    const int rr = t >> 5, c4 = t & 31;
#pragma unroll
    for (int i = 0; i < 4; ++i) {
        const int row = rr + 8 * i;
        const size_t off = ((size_t)(b0 + row) * HIDDEN) + c4 * 4;
        float4 a = *(const float4*)&Tp[off];
        float4 b = *(const float4*)&Tp[(size_t)BATCH * HIDDEN + off];
        sm[row][c4 * 4 + 0] = a.x + b.x;
        sm[row][c4 * 4 + 1] = a.y + b.y;
        sm[row][c4 * 4 + 2] = a.z + b.z;
        sm[row][c4 * 4 + 3] = a.w + b.w;
    }
    __syncthreads();
    const int w = t >> 5, l = t & 31;
#pragma unroll
    for (int i = 0; i < 16; ++i) {
        const int n = w + 8 * i;
        Tt[(size_t)n * BATCH + b0 + l] = sm[l][n];
    }
}

// ---------------------------------------------------------------------------
// final_norm: out[b] = normalize(Op0[b] + Op1[b])  (row L2), one warp per row
// ---------------------------------------------------------------------------
__global__ __launch_bounds__(256, 1)
void final_norm_kernel(const float* __restrict__ Op, float* __restrict__ outp) {
    const int t   = threadIdx.x;
    const int row = blockIdx.x * 8 + (t >> 5);
    const int l   = t & 31;
    const size_t off = (size_t)row * HIDDEN + l * 4;
    float4 a = *(const float4*)&Op[off];
    float4 b = *(const float4*)&Op[(size_t)BATCH * HIDDEN + off];
    float4 v = make_float4(a.x + b.x, a.y + b.y, a.z + b.z, a.w + b.w);
    float ss = v.x * v.x + v.y * v.y + v.z * v.z + v.w * v.w;
#pragma unroll
    for (int o = 16; o > 0; o >>= 1) ss += __shfl_xor_sync(0xFFFFFFFFu, ss, o);
    const float sc = rsqrtf(ss);
    v.x *= sc; v.y *= sc; v.z *= sc; v.w *= sc;
    *(float4*)&outp[off] = v;
}

// ---------------------------------------------------------------------------
// Host: tensormaps via driver entry point (through cudart; host-only, capture-safe)
// ---------------------------------------------------------------------------
typedef CUresult (*EncodeTiledFn)(CUtensorMap*, CUtensorMapDataType, cuuint32_t, void*,
                                  const cuuint64_t*, const cuuint64_t*, const cuuint32_t*,
                                  const cuuint32_t*, CUtensorMapInterleave, CUtensorMapSwizzle,
                                  CUtensorMapL2promotion, CUtensorMapFloatOOBfill);

static void make_map_2d(EncodeTiledFn enc, CUtensorMap* m, void* ptr,
                        uint64_t dim0, uint64_t dim1, uint32_t box0, uint32_t box1) {
    cuuint64_t dims[2]    = {dim0, dim1};
    cuuint64_t strides[1] = {dim0 * sizeof(float)};
    cuuint32_t box[2]     = {box0, box1};
    cuuint32_t estr[2]    = {1, 1};
    enc(m, CU_TENSOR_MAP_DATA_TYPE_FLOAT32, 2, ptr, dims, strides, box, estr,
        CU_TENSOR_MAP_INTERLEAVE_NONE, CU_TENSOR_MAP_SWIZZLE_128B,
        CU_TENSOR_MAP_L2_PROMOTION_L2_128B, CU_TENSOR_MAP_FLOAT_OOB_FILL_NONE);
}

// ---------------------------------------------------------------------------
// kernel_launch: inputs in metadata order:
//   d_in[0] item_embedding f32 (100000,128); d_in[1] items i32 (4096,50);
//   d_in[2] A f32 (4096,4096); d_in[3] D f32 (4096,4096); d_in[4] unused.
// Output: f32 (4096, 128)
// ---------------------------------------------------------------------------
extern "C" void kernel_launch(void* const* d_in, const int* in_sizes, int n_in,
                              void* d_out, int out_size) {
    const float* emb   = (const float*)d_in[0];
    const int*   items = (const int*)d_in[1];
    float*       A     = (float*)d_in[2];
    float*       D     = (float*)d_in[3];
    float*       out   = (float*)d_out;

    float *Rt, *Tp, *Tt, *Op;
    cudaGetSymbolAddress((void**)&Rt, g_Rt);
    cudaGetSymbolAddress((void**)&Tp, g_Tp);
    cudaGetSymbolAddress((void**)&Tt, g_Tt);
    cudaGetSymbolAddress((void**)&Op, g_Op);

    void* fn = nullptr;
    cudaDriverEntryPointQueryResult qr;
    cudaGetDriverEntryPoint("cuTensorMapEncodeTiled", &fn, cudaEnableDefault, &qr);
    EncodeTiledFn enc = (EncodeTiledFn)fn;

    CUtensorMap mA, mR, mD, mT;
    make_map_2d(enc, &mA, A,  KDIM, BATCH,  32, BM);      // A  [4096 m][4096 k]
    make_map_2d(enc, &mR, Rt, BATCH, HIDDEN, 32, HIDDEN); // Rt [128 n][4096 k]
    make_map_2d(enc, &mD, D,  KDIM, BATCH,  32, BM);      // D
    make_map_2d(enc, &mT, Tt, BATCH, HIDDEN, 32, HIDDEN); // Tt

    cudaFuncSetAttribute(gemm_part_kernel, cudaFuncAttributeMaxDynamicSharedMemorySize, SMEM_DYN);

    // 1) R^T = gather-sum (transposed; warp-per-row float4)
    gather_t_kernel<<<BATCH / 32, 1024>>>(emb, items, Rt);
    // 2) Tp[kh] = A[:, kh] @ R[kh]  (K-split partials)
    gemm_part_kernel<<<(BATCH / BM) * KSPLIT, NTHREADS, SMEM_DYN>>>(mA, mR, Tp);
    // 3) Tt = transpose(Tp0 + Tp1)
    reduce_t_kernel<<<BATCH / 32, 256>>>(Tp, Tt);
    // 4) Op[kh] = D[:, kh] @ T[kh]
    gemm_part_kernel<<<(BATCH / BM) * KSPLIT, NTHREADS, SMEM_DYN>>>(mD, mT, Op);
    // 5) out = normalize_rows(Op0 + Op1)
    final_norm_kernel<<<BATCH / 8, 256>>>(Op, out);
}

// round 17
// speedup vs baseline: 1.1178x; 1.0729x over previous
#include <cuda_runtime.h>
#include <cuda.h>
#include <cstdint>

// ---------------------------------------------------------------------------
// Problem dims (fixed by the dataset)
// ---------------------------------------------------------------------------
#define HIDDEN 128
#define BATCH  4096
#define SESS   50
#define KDIM   4096

// GEMM tiling: R14 validated config (KC=64 via 2 chunks, NSTAGES=4, occ 1).
#define BM       64
#define KSPLIT   2
#define KHALF    (KDIM / KSPLIT)   // 2048
#define KC       64                // K floats per stage (2 chunks of 32)
#define NITER    (KHALF / KC)      // 32
#define NSTAGES  4
#define NCONS    8                 // consumer warps
#define NTHREADS (NCONS * 32 + 32) // 288
#define A_CH_BYTES (BM * 32 * 4)       // 8192  per 32-col chunk
#define B_CH_BYTES (HIDDEN * 32 * 4)   // 16384 per 32-col chunk
#define A_ST_BYTES (2 * A_CH_BYTES)    // 16384
#define B_ST_BYTES (2 * B_CH_BYTES)    // 32768
#define STAGE_BYTES (A_ST_BYTES + B_ST_BYTES)         // 49152
#define SM_BAR      (NSTAGES * STAGE_BYTES)           // 196608 (192KB, occ 1)
#define SMEM_DYN    (SM_BAR + 128)

// ---------------------------------------------------------------------------
// Scratch (allocation-free rule: __device__ globals)
// ---------------------------------------------------------------------------
__device__ float g_Rt[HIDDEN * BATCH];          // R^T  [n=128][k=4096]
__device__ float g_Tp[KSPLIT * BATCH * HIDDEN]; // GEMM1 partials, row-major
__device__ float g_Tt[HIDDEN * BATCH];          // T^T  [n=128][k=4096]
__device__ float g_Op[KSPLIT * BATCH * HIDDEN]; // GEMM2 partials, row-major

// ---------------------------------------------------------------------------
// PTX helpers (sm_90-portable; NO tcgen05)
// ---------------------------------------------------------------------------
__device__ __forceinline__ uint32_t smem_u32(const void* p) {
    uint32_t a;
    asm("{ .reg .u64 t; cvta.to.shared.u64 t, %1; cvt.u32.u64 %0, t; }" : "=r"(a) : "l"(p));
    return a;
}
__device__ __forceinline__ uint32_t elect_one() {
    uint32_t p;
    asm volatile("{\n\t.reg .pred p;\n\telect.sync _|p, 0xFFFFFFFF;\n\tselp.b32 %0, 1, 0, p;\n\t}" : "=r"(p));
    return p;
}
#define MBAR_INIT(addr, cnt) \
    asm volatile("mbarrier.init.shared.b64 [%0], %1;" :: "r"((uint32_t)(addr)), "r"((uint32_t)(cnt)) : "memory")
#define MBAR_ARRIVE(addr) \
    asm volatile("mbarrier.arrive.shared.b64 _, [%0];" :: "r"((uint32_t)(addr)) : "memory")
#define MBAR_EXPECT_TX(addr, bytes) \
    asm volatile("mbarrier.arrive.expect_tx.shared.b64 _, [%0], %1;" :: "r"((uint32_t)(addr)), "r"((uint32_t)(bytes)) : "memory")
#define FENCE_PROXY_ASYNC() asm volatile("fence.proxy.async;" ::: "memory")

#define MBAR_WAIT(addr, parity) do {                                             \
    uint32_t _m = (uint32_t)(addr); uint32_t _p = (uint32_t)(parity);            \
    asm volatile("{\n\t.reg .pred P1;\n\t"                                       \
        "WL_%=:\n\t"                                                             \
        "mbarrier.try_wait.parity.acquire.cta.shared::cta.b64 P1, [%0], %1, 0x989680;\n\t" \
        "@P1 bra.uni WD_%=;\n\t"                                                 \
        "bra.uni WL_%=;\n\t"                                                     \
        "WD_%=:\n\t}" :: "r"(_m), "r"(_p) : "memory");                           \
} while (0)

#define MBAR_WAIT_RELAXED(addr, parity) do {                                     \
    uint32_t _m = (uint32_t)(addr); uint32_t _p = (uint32_t)(parity);            \
    asm volatile("{\n\t.reg .pred P1;\n\t"                                       \
        "WL_%=:\n\t"                                                             \
        "mbarrier.try_wait.parity.relaxed.cta.shared::cta.b64 P1, [%0], %1, 0x989680;\n\t" \
        "@P1 bra.uni WD_%=;\n\t"                                                 \
        "bra.uni WL_%=;\n\t"                                                     \
        "WD_%=:\n\t}" :: "r"(_m), "r"(_p) : "memory");                           \
} while (0)

#define TMA_LOAD2D(smem_addr, tmap_ptr, cx, cy, mbar)                                            \
    asm volatile("cp.async.bulk.tensor.2d.shared::cta.global.tile.mbarrier::complete_tx::bytes " \
                 "[%0], [%1, {%2, %3}], [%4];"                                                   \
                 :: "r"((uint32_t)(smem_addr)), "l"(tmap_ptr), "r"((int)(cx)), "r"((int)(cy)),   \
                    "r"((uint32_t)(mbar)) : "memory")

__device__ __forceinline__ void ldmatrix_x4(uint32_t* r, uint32_t addr) {
    asm volatile("ldmatrix.sync.aligned.m8n8.x4.shared.b16 {%0,%1,%2,%3}, [%4];"
                 : "=r"(r[0]), "=r"(r[1]), "=r"(r[2]), "=r"(r[3]) : "r"(addr));
}
__device__ __forceinline__ void mma_tf32(float* c,
                                         uint32_t a0, uint32_t a1, uint32_t a2, uint32_t a3,
                                         uint32_t b0, uint32_t b1) {
    asm volatile("mma.sync.aligned.m16n8k8.row.col.f32.tf32.tf32.f32 "
                 "{%0,%1,%2,%3}, {%4,%5,%6,%7}, {%8,%9}, {%0,%1,%2,%3};"
                 : "+f"(c[0]), "+f"(c[1]), "+f"(c[2]), "+f"(c[3])
                 : "r"(a0), "r"(a1), "r"(a2), "r"(a3), "r"(b0), "r"(b1));
}

// ---------------------------------------------------------------------------
// Kernel 1: gather+sum, output TRANSPOSED: Rt[h][b] = sum_s emb[items[b,s]][h]
// 128 blocks x 1024 threads; ONE WARP PER SESSION ROW; float4 loads.
// ---------------------------------------------------------------------------
__global__ __launch_bounds__(1024, 1)
void gather_t_kernel(const float* __restrict__ emb,
                     const int* __restrict__ items,
                     float* __restrict__ Rt) {
    __shared__ float sm[32][132];
    const int t  = threadIdx.x;
    const int w  = t >> 5;
    const int l  = t & 31;
    const int b0 = blockIdx.x * 32;

    const int* it = items + (b0 + w) * SESS;
    float4 acc = make_float4(0.f, 0.f, 0.f, 0.f);
#pragma unroll 10
    for (int s = 0; s < SESS; ++s) {
        const long long idx = (long long)it[s];
        const float4 v = *(const float4*)&emb[idx * HIDDEN + l * 4];
        acc.x += v.x; acc.y += v.y; acc.z += v.z; acc.w += v.w;
    }
    *(float4*)&sm[w][l * 4] = acc;
    __syncthreads();

#pragma unroll
    for (int i = 0; i < 4; ++i) {
        const int hh = w * 4 + i;
        Rt[(size_t)hh * BATCH + b0 + l] = sm[l][hh];
    }
}

// ---------------------------------------------------------------------------
// GEMM (partial K):  Cp[kh] = Amat[:, kh-half] @ B[kh-half]
// Grid 128: kh = bx & 1, mtile = bx >> 1.  288 threads, occ 1 (192KB smem):
// 8 consumer warps (2M x 2N x 2 K-interleave, warp tile 32x64) + 1 TMA warp.
// R17: all 24 stage LDSMs issued first, EMPTY-ARRIVE immediately after (stage
// handed back to producer ~one MMA-stream earlier), then the 64-MMA stream.
// Next-stage wait remains at loop top (never before ready work).
// ---------------------------------------------------------------------------
__global__ __launch_bounds__(NTHREADS, 1)
void gemm_part_kernel(const __grid_constant__ CUtensorMap tA,
                      const __grid_constant__ CUtensorMap tB,
                      float* __restrict__ Cp) {
    extern __shared__ char smem[];
    const uint32_t sb = smem_u32(smem);
    const int tid = threadIdx.x;
    const int wid = tid >> 5;
    const int l   = tid & 31;
    const int kh    = blockIdx.x & 1;
    const int mtile = blockIdx.x >> 1;
    const int m0    = mtile * BM;

    if (tid == 0) {
#pragma unroll
        for (int s = 0; s < NSTAGES; ++s) {
            MBAR_INIT(sb + SM_BAR + s * 8, 1);          // full: tx-based
            MBAR_INIT(sb + SM_BAR + 64 + s * 8, NCONS); // empty: 8 consumer warps
        }
        FENCE_PROXY_ASYNC();
    }
    __syncthreads();

    if (wid == NCONS) {
        // -------- producer: 4 TMA loads per stage (2 chunks x {A,B}) --------
        if (elect_one()) {
            int s = 0, ph = 1;
            for (int it = 0; it < NITER; ++it) {
                MBAR_WAIT_RELAXED(sb + SM_BAR + 64 + s * 8, ph);
                MBAR_EXPECT_TX(sb + SM_BAR + s * 8, STAGE_BYTES);
                const int kc = kh * KHALF + it * KC;
                const uint32_t st = sb + s * STAGE_BYTES;
                TMA_LOAD2D(st,                           &tA, kc,      m0, sb + SM_BAR + s * 8);
                TMA_LOAD2D(st + A_CH_BYTES,              &tA, kc + 32, m0, sb + SM_BAR + s * 8);
                TMA_LOAD2D(st + A_ST_BYTES,              &tB, kc,      0,  sb + SM_BAR + s * 8);
                TMA_LOAD2D(st + A_ST_BYTES + B_CH_BYTES, &tB, kc + 32, 0,  sb + SM_BAR + s * 8);
                if (++s == NSTAGES) { s = 0; ph ^= 1; }
            }
        }
        return;
    }

    // -------- consumers: 8 warps = 2M x 2N x 2(K-interleave) --------
    const int wm = wid & 1;           // M half (32 rows)
    const int wn = (wid >> 1) & 1;    // N half (64 cols)
    const int ws = wid >> 2;          // K-interleave half within each chunk
    const int g = l >> 2, tq = l & 3;
    const int j = l >> 3, r = l & 7;

    // ldmatrix per-lane address components (byte offsets within a chunk)
    const int aRow0 = wm * 32 + (j & 1) * 8 + r;
    const uint32_t aOff0 = (uint32_t)(aRow0 * 128);
    const uint32_t aOff1 = (uint32_t)((aRow0 + 16) * 128);
    const uint32_t aSw0  = (uint32_t)((aRow0 & 7) << 4);
    const uint32_t aSw1  = (uint32_t)(((aRow0 + 16) & 7) << 4);
    const uint32_t aKsel = (uint32_t)((j >> 1) << 4);
    const int bRowBase = wn * 64 + (j >> 1) * 8 + r;
    const uint32_t bKsel = (uint32_t)((j & 1) << 4);

    float acc[2][8][4];
#pragma unroll
    for (int a = 0; a < 2; ++a)
#pragma unroll
        for (int b = 0; b < 8; ++b)
#pragma unroll
            for (int c = 0; c < 4; ++c) acc[a][b][c] = 0.f;

    int s = 0, ph = 0;
    for (int it = 0; it < NITER; ++it) {
        MBAR_WAIT(sb + SM_BAR + s * 8, ph);
        const uint32_t stBase = sb + s * STAGE_BYTES;

        // ---- Phase 1: issue ALL stage fragment loads (both chunks, both ki) --
        uint32_t af[2][2][2][4];   // [ch][ki][mt][4]
        uint32_t bf[2][2][4][4];   // [ch][ki][nt16][4]
#pragma unroll
        for (int ch = 0; ch < 2; ++ch) {
            const uint32_t aBase = stBase + ch * A_CH_BYTES;
            const uint32_t bBase = stBase + A_ST_BYTES + ch * B_CH_BYTES;
#pragma unroll
            for (int ki = 0; ki < 2; ++ki) {
                const uint32_t kb = (uint32_t)((ws * 2 + ki) * 32);
                ldmatrix_x4(af[ch][ki][0], aBase + aOff0 + ((kb + aKsel) ^ aSw0));
                ldmatrix_x4(af[ch][ki][1], aBase + aOff1 + ((kb + aKsel) ^ aSw1));
#pragma unroll
                for (int nt16 = 0; nt16 < 4; ++nt16) {
                    const int nrow = bRowBase + nt16 * 16;
                    ldmatrix_x4(bf[ch][ki][nt16],
                                bBase + (uint32_t)(nrow * 128) + ((kb + bKsel) ^ (uint32_t)((nrow & 7) << 4)));
                }
            }
        }
        // ---- Stage fully read (ldmatrix is synchronous): hand it back NOW ----
        if (elect_one()) MBAR_ARRIVE(sb + SM_BAR + 64 + s * 8);

        // ---- Phase 2: 64-MMA stream (same accumulation order as R14) --------
#pragma unroll
        for (int ch = 0; ch < 2; ++ch)
#pragma unroll
            for (int ki = 0; ki < 2; ++ki)
#pragma unroll
                for (int mt = 0; mt < 2; ++mt)
#pragma unroll
                    for (int nt = 0; nt < 8; ++nt) {
                        const uint32_t* bp = bf[ch][ki][nt >> 1] + (nt & 1) * 2;
                        mma_tf32(acc[mt][nt],
                                 af[ch][ki][mt][0], af[ch][ki][mt][1],
                                 af[ch][ki][mt][2], af[ch][ki][mt][3],
                                 bp[0], bp[1]);
                    }

        if (++s == NSTAGES) { s = 0; ph ^= 1; }
    }

    // -------- epilogue: combine the two ws-halves through smem, then store ----
    asm volatile("bar.sync 1, %0;" :: "n"(NCONS * 32) : "memory");
    float* red = (float*)smem;   // 4 groups x 32 lanes x 64 floats = 32KB
    const int rbase = ((wm * 2 + wn) * 32 + l) * 64;
    if (ws == 1) {
#pragma unroll
        for (int mt = 0; mt < 2; ++mt)
#pragma unroll
            for (int nt = 0; nt < 8; ++nt) {
                float* d = red + rbase + (mt * 8 + nt) * 4;
                d[0] = acc[mt][nt][0]; d[1] = acc[mt][nt][1];
                d[2] = acc[mt][nt][2]; d[3] = acc[mt][nt][3];
            }
    }
    asm volatile("bar.sync 1, %0;" :: "n"(NCONS * 32) : "memory");
    if (ws == 0) {
        float* outp = Cp + (size_t)kh * BATCH * HIDDEN;
#pragma unroll
        for (int mt = 0; mt < 2; ++mt)
#pragma unroll
            for (int nt = 0; nt < 8; ++nt) {
                const float* d = red + rbase + (mt * 8 + nt) * 4;
                const int row = m0 + wm * 32 + mt * 16 + g;
                const int col = wn * 64 + nt * 8 + tq * 2;
                float2 v0 = make_float2(acc[mt][nt][0] + d[0], acc[mt][nt][1] + d[1]);
                float2 v1 = make_float2(acc[mt][nt][2] + d[2], acc[mt][nt][3] + d[3]);
                *(float2*)&outp[(size_t)row * HIDDEN + col]       = v0;
                *(float2*)&outp[(size_t)(row + 8) * HIDDEN + col] = v1;
            }
    }
}

// ---------------------------------------------------------------------------
// reduce_T: Tt[n][b] = Tp0[b][n] + Tp1[b][n]   (transpose + add)
// ---------------------------------------------------------------------------
__global__ __launch_bounds__(256, 1)
void reduce_t_kernel(const float* __restrict__ Tp, float* __restrict__ Tt) {
    __shared__ float sm[32][129];
    const int t  = threadIdx.x;
    const int b0 = blockIdx.x * 32;
    const int rr = t >> 5, c4 = t & 31;
#pragma unroll
    for (int i = 0; i < 4; ++i) {
        const int row = rr + 8 * i;
        const size_t off = ((size_t)(b0 + row) * HIDDEN) + c4 * 4;
        float4 a = *(const float4*)&Tp[off];
        float4 b = *(const float4*)&Tp[(size_t)BATCH * HIDDEN + off];
        sm[row][c4 * 4 + 0] = a.x + b.x;
        sm[row][c4 * 4 + 1] = a.y + b.y;
        sm[row][c4 * 4 + 2] = a.z + b.z;
        sm[row][c4 * 4 + 3] = a.w + b.w;
    }
    __syncthreads();
    const int w = t >> 5, l = t & 31;
#pragma unroll
    for (int i = 0; i < 16; ++i) {
        const int n = w + 8 * i;
        Tt[(size_t)n * BATCH + b0 + l] = sm[l][n];
    }
}

// ---------------------------------------------------------------------------
// final_norm: out[b] = normalize(Op0[b] + Op1[b])  (row L2), one warp per row
// ---------------------------------------------------------------------------
__global__ __launch_bounds__(256, 1)
void final_norm_kernel(const float* __restrict__ Op, float* __restrict__ outp) {
    const int t   = threadIdx.x;
    const int row = blockIdx.x * 8 + (t >> 5);
    const int l   = t & 31;
    const size_t off = (size_t)row * HIDDEN + l * 4;
    float4 a = *(const float4*)&Op[off];
    float4 b = *(const float4*)&Op[(size_t)BATCH * HIDDEN + off];
    float4 v = make_float4(a.x + b.x, a.y + b.y, a.z + b.z, a.w + b.w);
    float ss = v.x * v.x + v.y * v.y + v.z * v.z + v.w * v.w;
#pragma unroll
    for (int o = 16; o > 0; o >>= 1) ss += __shfl_xor_sync(0xFFFFFFFFu, ss, o);
    const float sc = rsqrtf(ss);
    v.x *= sc; v.y *= sc; v.z *= sc; v.w *= sc;
    *(float4*)&outp[off] = v;
}

// ---------------------------------------------------------------------------
// Host: tensormaps via driver entry point (through cudart; host-only, capture-safe)
// ---------------------------------------------------------------------------
typedef CUresult (*EncodeTiledFn)(CUtensorMap*, CUtensorMapDataType, cuuint32_t, void*,
                                  const cuuint64_t*, const cuuint64_t*, const cuuint32_t*,
                                  const cuuint32_t*, CUtensorMapInterleave, CUtensorMapSwizzle,
                                  CUtensorMapL2promotion, CUtensorMapFloatOOBfill);

static void make_map_2d(EncodeTiledFn enc, CUtensorMap* m, void* ptr,
                        uint64_t dim0, uint64_t dim1, uint32_t box0, uint32_t box1) {
    cuuint64_t dims[2]    = {dim0, dim1};
    cuuint64_t strides[1] = {dim0 * sizeof(float)};
    cuuint32_t box[2]     = {box0, box1};
    cuuint32_t estr[2]    = {1, 1};
    enc(m, CU_TENSOR_MAP_DATA_TYPE_FLOAT32, 2, ptr, dims, strides, box, estr,
        CU_TENSOR_MAP_INTERLEAVE_NONE, CU_TENSOR_MAP_SWIZZLE_128B,
        CU_TENSOR_MAP_L2_PROMOTION_L2_128B, CU_TENSOR_MAP_FLOAT_OOB_FILL_NONE);
}

// ---------------------------------------------------------------------------
// kernel_launch: inputs in metadata order:
//   d_in[0] item_embedding f32 (100000,128); d_in[1] items i32 (4096,50);
//   d_in[2] A f32 (4096,4096); d_in[3] D f32 (4096,4096); d_in[4] unused.
// Output: f32 (4096, 128)
// ---------------------------------------------------------------------------
extern "C" void kernel_launch(void* const* d_in, const int* in_sizes, int n_in,
                              void* d_out, int out_size) {
    const float* emb   = (const float*)d_in[0];
    const int*   items = (const int*)d_in[1];
    float*       A     = (float*)d_in[2];
    float*       D     = (float*)d_in[3];
    float*       out   = (float*)d_out;

    float *Rt, *Tp, *Tt, *Op;
    cudaGetSymbolAddress((void**)&Rt, g_Rt);
    cudaGetSymbolAddress((void**)&Tp, g_Tp);
    cudaGetSymbolAddress((void**)&Tt, g_Tt);
    cudaGetSymbolAddress((void**)&Op, g_Op);

    void* fn = nullptr;
    cudaDriverEntryPointQueryResult qr;
    cudaGetDriverEntryPoint("cuTensorMapEncodeTiled", &fn, cudaEnableDefault, &qr);
    EncodeTiledFn enc = (EncodeTiledFn)fn;

    CUtensorMap mA, mR, mD, mT;
    make_map_2d(enc, &mA, A,  KDIM, BATCH,  32, BM);      // A  [4096 m][4096 k]
    make_map_2d(enc, &mR, Rt, BATCH, HIDDEN, 32, HIDDEN); // Rt [128 n][4096 k]
    make_map_2d(enc, &mD, D,  KDIM, BATCH,  32, BM);      // D
    make_map_2d(enc, &mT, Tt, BATCH, HIDDEN, 32, HIDDEN); // Tt

    cudaFuncSetAttribute(gemm_part_kernel, cudaFuncAttributeMaxDynamicSharedMemorySize, SMEM_DYN);

    // 1) R^T = gather-sum (transposed; warp-per-row float4)
    gather_t_kernel<<<BATCH / 32, 1024>>>(emb, items, Rt);
    // 2) Tp[kh] = A[:, kh] @ R[kh]  (K-split partials)
    gemm_part_kernel<<<(BATCH / BM) * KSPLIT, NTHREADS, SMEM_DYN>>>(mA, mR, Tp);
    // 3) Tt = transpose(Tp0 + Tp1)
    reduce_t_kernel<<<BATCH / 32, 256>>>(Tp, Tt);
    // 4) Op[kh] = D[:, kh] @ T[kh]
    gemm_part_kernel<<<(BATCH / BM) * KSPLIT, NTHREADS, SMEM_DYN>>>(mD, mT, Op);
    // 5) out = normalize_rows(Op0 + Op1)
    final_norm_kernel<<<BATCH / 8, 256>>>(Op, out);
}